// round 9
// baseline (speedup 1.0000x reference)
#include <cuda_runtime.h>
#include <cstdint>

// YOLO post-process: (16, 25200, 85) fp32 -> (16, 25200, 6) fp32
//
// R8: static contiguous chunks (R7) + depth-3 cp.async.bulk pipeline
//     (96-row / 32640B tiles, 96 threads, 2 blocks/SM) + direct STG epilogue
//     (no output staging). Copy queue holds 1-2 pending DMAs per block at all
//     times, including through the compute/store window.

#define N_ROWS        403200          // 16 * 25200
#define N_CH          85
#define N_OUT         6
#define CONF_TH       0.25f
#define TILE_ROWS     96
#define BLOCK_THREADS 96
#define DEPTH         3
#define TILE_FLOATS   (TILE_ROWS * N_CH)     // 8160
#define TILE_BYTES    (TILE_FLOATS * 4)      // 32640
#define GRID_BLOCKS   296                    // 2 per SM * 148

// Chunking in quad-rows (4 rows => every bulk-copy source 16B-aligned):
//   total quads = 100800 = 296*340 + 160 -> first 160 blocks get 341 quads.
#define QUADS_BASE    340
#define QUADS_EXTRA   160

// dynamic smem: [0,24) mbar[3], [32, +3*TILE_BYTES) in bufs
#define SM_IN    32
#define SM_TOTAL (SM_IN + DEPTH * TILE_BYTES)        // 97952

__device__ __forceinline__ unsigned smem_u32(const void* p) {
    unsigned a;
    asm("{ .reg .u64 t; cvta.to.shared.u64 t, %1; cvt.u32.u64 %0, t; }"
        : "=r"(a) : "l"(p));
    return a;
}

__device__ __forceinline__ void mbar_init(unsigned addr, unsigned count) {
    asm volatile("mbarrier.init.shared.b64 [%0], %1;" :: "r"(addr), "r"(count) : "memory");
}

__device__ __forceinline__ void bulk_load(unsigned dst_smem, const void* gsrc,
                                          unsigned bytes, unsigned mbar) {
    asm volatile("mbarrier.arrive.expect_tx.shared.b64 _, [%0], %1;"
                 :: "r"(mbar), "r"(bytes) : "memory");
    asm volatile("cp.async.bulk.shared::cta.global.mbarrier::complete_tx::bytes "
                 "[%0], [%1], %2, [%3];"
                 :: "r"(dst_smem), "l"(gsrc), "r"(bytes), "r"(mbar) : "memory");
}

__device__ __forceinline__ void mbar_wait(unsigned addr, unsigned parity) {
    asm volatile(
        "{\n\t"
        ".reg .pred P;\n\t"
        "W%=:\n\t"
        "mbarrier.try_wait.parity.acquire.cta.shared::cta.b64 P, [%0], %1, 0x989680;\n\t"
        "@P bra D%=;\n\t"
        "bra W%=;\n\t"
        "D%=:\n\t"
        "}"
        :: "r"(addr), "r"(parity) : "memory");
}

__global__ __launch_bounds__(BLOCK_THREADS, 2)
void yolo_post_kernel(const float* __restrict__ in, float2* __restrict__ out2)
{
    extern __shared__ char sb[];
    const unsigned base = smem_u32(sb);
    float* const in_base = reinterpret_cast<float*>(sb + SM_IN);

    const int tid = threadIdx.x;
    const int b   = blockIdx.x;

    // Contiguous chunk (quad-row granularity).
    const int q_start = QUADS_BASE * b + (b < QUADS_EXTRA ? b : QUADS_EXTRA);
    const int row0    = 4 * q_start;
    const int n_rows  = 4 * (QUADS_BASE + (b < QUADS_EXTRA ? 1 : 0));   // 1364 or 1360
    const int n_tiles = (n_rows + TILE_ROWS - 1) / TILE_ROWS;           // 15

    if (tid == 0) {
        #pragma unroll
        for (int s = 0; s < DEPTH; s++) mbar_init(base + s * 8, 1);
        // Prologue: issue DMAs for tiles 0..DEPTH-2 into slots 0..DEPTH-2.
        #pragma unroll
        for (int s = 0; s < DEPTH - 1; s++) {
            if (s < n_tiles) {
                int tr = n_rows - s * TILE_ROWS;
                if (tr > TILE_ROWS) tr = TILE_ROWS;
                bulk_load(base + SM_IN + s * TILE_BYTES,
                          in + (size_t)(row0 + s * TILE_ROWS) * N_CH,
                          (unsigned)(tr * N_CH * 4), base + s * 8);
            }
        }
    }
    __syncthreads();

    for (int it = 0; it < n_tiles; ++it) {
        const int slot = it % DEPTH;

        // Issue DMA for tile it+DEPTH-1 into slot (it+DEPTH-1)%DEPTH
        // == (it-1)%DEPTH: consumed in iteration it-1, fenced by its sync.
        const int t_iss = it + DEPTH - 1;
        if (tid == 0 && t_iss < n_tiles) {
            const int slot_w = t_iss % DEPTH;
            int tr = n_rows - t_iss * TILE_ROWS;
            if (tr > TILE_ROWS) tr = TILE_ROWS;
            bulk_load(base + SM_IN + slot_w * TILE_BYTES,
                      in + (size_t)(row0 + t_iss * TILE_ROWS) * N_CH,
                      (unsigned)(tr * N_CH * 4), base + slot_w * 8);
        }

        // Wait for the current tile (slot reused every DEPTH iterations).
        mbar_wait(base + slot * 8, (unsigned)((it / DEPTH) & 1));

        const int r_off = it * TILE_ROWS;
        int tile_rows = n_rows - r_off;
        if (tile_rows > TILE_ROWS) tile_rows = TILE_ROWS;

        // ---- compute: thread-per-row (stride-85 LDS = conflict-free) ----
        if (tid < tile_rows) {
            const float* row = in_base + slot * TILE_FLOATS + tid * N_CH;

            const float x    = row[0];
            const float y    = row[1];
            const float w    = row[2];
            const float h    = row[3];
            const float conf = row[4];

            float b0 = row[5 +  0], b1 = row[5 + 20], b2 = row[5 + 40], b3 = row[5 + 60];
            int   i0 = 0,           i1 = 20,          i2 = 40,          i3 = 60;

            #pragma unroll
            for (int c = 1; c < 20; c++) {
                float v0 = row[5 +  0 + c];
                float v1 = row[5 + 20 + c];
                float v2 = row[5 + 40 + c];
                float v3 = row[5 + 60 + c];
                if (v0 > b0) { b0 = v0; i0 =  0 + c; }
                if (v1 > b1) { b1 = v1; i1 = 20 + c; }
                if (v2 > b2) { b2 = v2; i2 = 40 + c; }
                if (v3 > b3) { b3 = v3; i3 = 60 + c; }
            }
            // Ordered merge: ties keep the earlier quarter -> first-index semantics.
            if (b1 > b0) { b0 = b1; i0 = i1; }
            if (b2 > b0) { b0 = b2; i0 = i2; }
            if (b3 > b0) { b0 = b3; i0 = i3; }

            const float score = conf * b0;
            const bool  pass  = score > CONF_TH;
            const float hw = 0.5f * w;
            const float hh = 0.5f * h;

            float o0 = 0.f, o1 = 0.f, o2 = 0.f, o3 = 0.f, o4 = 0.f, o5 = 0.f;
            if (pass) {
                o0 = x - hw;
                o1 = y - hh;
                o2 = x + hw;
                o3 = y + hh;
                o4 = score;
                o5 = (float)i0;
            }

            // Direct epilogue: 3x STG.64, 8B-aligned (row*24 % 8 == 0).
            float2* dst = out2 + (size_t)(row0 + r_off + tid) * 3;
            dst[0] = make_float2(o0, o1);
            dst[1] = make_float2(o2, o3);
            dst[2] = make_float2(o4, o5);
        }
        // Fence: all LDS reads of this slot done before it is re-filled
        // (re-fill happens at top of iteration it+1, for slot (it)%DEPTH... 
        //  specifically slot reuse occurs DEPTH-1 iterations later, after this sync).
        __syncthreads();
    }
}

extern "C" void kernel_launch(void* const* d_in, const int* in_sizes, int n_in,
                              void* d_out, int out_size)
{
    const float* in  = (const float*)d_in[0];
    float2*      out = (float2*)d_out;
    cudaFuncSetAttribute(yolo_post_kernel,
                         cudaFuncAttributeMaxDynamicSharedMemorySize, SM_TOTAL);
    yolo_post_kernel<<<GRID_BLOCKS, BLOCK_THREADS, SM_TOTAL>>>(in, out);
}